// round 1
// baseline (speedup 1.0000x reference)
#include <cuda_runtime.h>

// Model_55645596287458: rotate 4M points into camera frame, mask by
// depth (1,10) + FOV, emit masked verts [N,3] and loss = 1/(sum(obs)+eps),
// obs = exp(-((d-4)^2)/8) over masked points.
//
// Single fused kernel:
//  - R (Rx@Ry@Rz) + T computed once per block in shared memory
//  - 4 points per thread via 3x float4 loads / 3x float4 stores
//  - block-level reduction + atomicAdd; last block finalizes loss and
//    resets global accumulators (graph-replay safe, deterministic state)

__device__ float        g_sum   = 0.0f;
__device__ unsigned int g_count = 0u;

__global__ __launch_bounds__(256) void pose_obs_kernel(
    const float* __restrict__ pts,
    const float* __restrict__ px,  const float* __restrict__ py,
    const float* __restrict__ pz,  const float* __restrict__ proll,
    const float* __restrict__ ppitch, const float* __restrict__ pyaw,
    float* __restrict__ out, int n_pts, int loss_idx)
{
    __shared__ float sRT[12];
    __shared__ float swarp[8];

    if (threadIdx.x == 0) {
        float roll = *proll, pitch = *ppitch, yaw = *pyaw;
        float cr = cosf(roll),  sr = sinf(roll);
        float cp = cosf(pitch), sp = sinf(pitch);
        float cy = cosf(yaw),   sy = sinf(yaw);
        // R = Rx @ Ry @ Rz (row-major)
        sRT[0] = cp * cy;                sRT[1] = -cp * sy;               sRT[2] = sp;
        sRT[3] = cr * sy + sr * sp * cy; sRT[4] = cr * cy - sr * sp * sy; sRT[5] = -sr * cp;
        sRT[6] = sr * sy - cr * sp * cy; sRT[7] = sr * cy + cr * sp * sy; sRT[8] = cr * cp;
        sRT[9] = *px; sRT[10] = *py; sRT[11] = *pz;
    }
    __syncthreads();

    const float R00 = sRT[0], R01 = sRT[1], R02 = sRT[2];
    const float R10 = sRT[3], R11 = sRT[4], R12 = sRT[5];
    const float R20 = sRT[6], R21 = sRT[7], R22 = sRT[8];
    const float Tx  = sRT[9], Ty  = sRT[10], Tz = sRT[11];

    const int n_groups = n_pts >> 2;        // 4 points per group
    const int g = blockIdx.x * blockDim.x + threadIdx.x;

    float obs_sum = 0.0f;

    if (g < n_groups) {
        const float4* __restrict__ P4 = (const float4*)pts;
        float4* __restrict__ O4 = (float4*)out;

        const float4 a = P4[3 * g + 0];
        const float4 b = P4[3 * g + 1];
        const float4 c = P4[3 * g + 2];

        float p[12] = {a.x, a.y, a.z, a.w, b.x, b.y, b.z, b.w, c.x, c.y, c.z, c.w};
        float o[12];

        #pragma unroll
        for (int i = 0; i < 4; i++) {
            const float d0 = p[3 * i + 0] - Tx;
            const float d1 = p[3 * i + 1] - Ty;
            const float d2 = p[3 * i + 2] - Tz;
            // v = d @ R  (v_j = sum_i d_i * R[i][j])
            const float v0 = fmaf(d2, R20, fmaf(d1, R10, d0 * R00));
            const float v1 = fmaf(d2, R21, fmaf(d1, R11, d0 * R01));
            const float v2 = fmaf(d2, R22, fmaf(d1, R12, d0 * R02));

            // ph = v @ K^T ; ph2 == v2 exactly (K row 2 = [0,0,1])
            const float ph0 = fmaf(600.0f, v0, 640.0f * v2);
            const float ph1 = fmaf(600.0f, v1, 360.0f * v2);
            const float inv = __fdividef(1.0f, v2);
            const float u = ph0 * inv;
            const float w = ph1 * inv;

            // v2 > 1 subsumes ph2 > 0
            const bool m = (v2 > 1.0f) & (v2 < 10.0f) &
                           (u > 1.0f) & (u < 1279.0f) &
                           (w > 1.0f) & (w < 719.0f);

            const float dist = sqrtf(fmaf(v0, v0, fmaf(v1, v1, v2 * v2)));
            const float t = (dist - 4.0f) * 0.5f;
            const float e = __expf(-0.5f * t * t);
            obs_sum += m ? e : 0.0f;

            o[3 * i + 0] = m ? v0 : 0.0f;
            o[3 * i + 1] = m ? v1 : 0.0f;
            o[3 * i + 2] = m ? v2 : 0.0f;
        }

        O4[3 * g + 0] = make_float4(o[0], o[1], o[2],  o[3]);
        O4[3 * g + 1] = make_float4(o[4], o[5], o[6],  o[7]);
        O4[3 * g + 2] = make_float4(o[8], o[9], o[10], o[11]);

        // Tail (n_pts not divisible by 4): scalar path on thread 0.
        if (g == 0) {
            for (int idx = n_groups * 4; idx < n_pts; idx++) {
                const float d0 = pts[3 * idx + 0] - Tx;
                const float d1 = pts[3 * idx + 1] - Ty;
                const float d2 = pts[3 * idx + 2] - Tz;
                const float v0 = fmaf(d2, R20, fmaf(d1, R10, d0 * R00));
                const float v1 = fmaf(d2, R21, fmaf(d1, R11, d0 * R01));
                const float v2 = fmaf(d2, R22, fmaf(d1, R12, d0 * R02));
                const float ph0 = fmaf(600.0f, v0, 640.0f * v2);
                const float ph1 = fmaf(600.0f, v1, 360.0f * v2);
                const float inv = __fdividef(1.0f, v2);
                const float u = ph0 * inv;
                const float w = ph1 * inv;
                const bool m = (v2 > 1.0f) & (v2 < 10.0f) &
                               (u > 1.0f) & (u < 1279.0f) &
                               (w > 1.0f) & (w < 719.0f);
                const float dist = sqrtf(fmaf(v0, v0, fmaf(v1, v1, v2 * v2)));
                const float t = (dist - 4.0f) * 0.5f;
                obs_sum += m ? __expf(-0.5f * t * t) : 0.0f;
                out[3 * idx + 0] = m ? v0 : 0.0f;
                out[3 * idx + 1] = m ? v1 : 0.0f;
                out[3 * idx + 2] = m ? v2 : 0.0f;
            }
        }
    }

    // ---- reduction: warp -> block -> global atomic ----
    #pragma unroll
    for (int off = 16; off > 0; off >>= 1)
        obs_sum += __shfl_xor_sync(0xffffffffu, obs_sum, off);

    const int lane = threadIdx.x & 31;
    const int wid  = threadIdx.x >> 5;
    if (lane == 0) swarp[wid] = obs_sum;
    __syncthreads();

    if (wid == 0) {
        float s = (lane < (blockDim.x >> 5)) ? swarp[lane] : 0.0f;
        #pragma unroll
        for (int off = 4; off > 0; off >>= 1)
            s += __shfl_xor_sync(0xffu, s, off);
        if (lane == 0) {
            atomicAdd(&g_sum, s);
            __threadfence();
            const unsigned int prev = atomicAdd(&g_count, 1u);
            if (prev == gridDim.x - 1u) {
                // atomicAdd(,0) forces an L2-coherent read of the total
                const float total = atomicAdd(&g_sum, 0.0f);
                out[loss_idx] = 1.0f / (total + 1e-6f);
                g_sum = 0.0f;       // reset for next graph replay
                g_count = 0u;
            }
        }
    }
}

extern "C" void kernel_launch(void* const* d_in, const int* in_sizes, int n_in,
                              void* d_out, int out_size) {
    const float* pts    = (const float*)d_in[0];
    const float* x      = (const float*)d_in[1];
    const float* y      = (const float*)d_in[2];
    const float* z      = (const float*)d_in[3];
    const float* roll   = (const float*)d_in[4];
    const float* pitch  = (const float*)d_in[5];
    const float* yaw    = (const float*)d_in[6];
    float* out = (float*)d_out;

    const int n_pts = in_sizes[0] / 3;       // 4,000,000
    const int n_groups = n_pts >> 2;         // 1,000,000
    const int threads = 256;
    const int blocks = (n_groups + threads - 1) / threads;
    const int loss_idx = out_size - 1;       // verts first, loss last

    pose_obs_kernel<<<blocks, threads>>>(pts, x, y, z, roll, pitch, yaw,
                                         out, n_pts, loss_idx);
}